// round 5
// baseline (speedup 1.0000x reference)
#include <cuda_runtime.h>
#include <cstdint>

// Problem constants (fixed by the reference): B=1, CIN=COUT=64, H=W=256, K=3, stride=1, pad=1.
#define IMG_H 256
#define IMG_W 256
#define NCH   64

// Scratch (device globals; no allocation allowed)
__device__ float g_xT[IMG_H * IMG_W * NCH];   // x transposed to (y, x, c) — 16 MB
__device__ float g_wT[9 * NCH * NCH];         // weights as (k, cin, cout)  — 147 KB

typedef unsigned long long u64;

// ---- packed fp32x2 helpers (Blackwell sm_100+) ----
__device__ __forceinline__ u64 fma2(u64 a, u64 b, u64 c) {
    u64 d;
    asm("fma.rn.f32x2 %0, %1, %2, %3;" : "=l"(d) : "l"(a), "l"(b), "l"(c));
    return d;
}
__device__ __forceinline__ u64 splat2(float x) {
    unsigned r = __float_as_uint(x);
    u64 d;
    asm("mov.b64 %0, {%1, %2};" : "=l"(d) : "r"(r), "r"(r));
    return d;
}
__device__ __forceinline__ float2 unpack2(u64 v) {
    unsigned lo, hi;
    asm("mov.b64 {%0, %1}, %2;" : "=r"(lo), "=r"(hi) : "l"(v));
    return make_float2(__uint_as_float(lo), __uint_as_float(hi));
}

// ============================================================
// Kernel 1: transpose x (C,H,W) -> (H,W,C), fully coalesced via smem tile
// ============================================================
__global__ void transpose_x_kernel(const float* __restrict__ x) {
    __shared__ float ts[64][65];
    const int t  = threadIdx.x;          // 256 threads
    const int tx = t & 63;
    const int ty = t >> 6;               // 0..3
    const int P0 = blockIdx.x * 64;      // 64 pixels per block

#pragma unroll
    for (int i = 0; i < 16; ++i) {
        int c = (i << 2) + ty;
        ts[c][tx] = x[c * (IMG_H * IMG_W) + P0 + tx];   // coalesced read
    }
    __syncthreads();
#pragma unroll
    for (int i = 0; i < 16; ++i) {
        int p = (i << 2) + ty;
        g_xT[(P0 + p) * 64 + tx] = ts[tx][p];           // coalesced write
    }
}

// ============================================================
// Kernel 2: weight relayout (cout,cin,k) -> (k,cin,cout)
// ============================================================
__global__ void prep_w_kernel(const float* __restrict__ wsrc) {
    int idx = blockIdx.x * blockDim.x + threadIdx.x;
    if (idx >= 64 * 64 * 9) return;
    int cout = idx / 576;
    int r    = idx - cout * 576;
    int cin  = r / 9;
    int k    = r - cin * 9;
    g_wT[(k * 64 + cin) * 64 + cout] = wsrc[idx];
}

// ============================================================
// Kernel 3: main deformable conv
//   Block: 8x8 output pixels, 128 threads (4 warps), 4 blocks/SM.
//   Phase A (per tap): bilinear-sample 64 channels from an smem halo tile
//                      into s[cin][px].
//   Phase B (per tap): register-blocked GEMM with packed fp32x2 FMA.
// ============================================================
__global__ __launch_bounds__(128, 4)
void deform_main_kernel(const float* __restrict__ offs,
                        const float* __restrict__ bias,
                        float* __restrict__ out) {
    // halo tile: 11 rows x 11 cols x 64 ch, XOR-swizzled in 16B chunks
    __shared__ float tile[121 * 64];     // 30976 B
    __shared__ float sbuf[64 * 64];      // 16384 B  (s[cin][px])

    const int t    = threadIdx.x;
    const int lane = t & 31;
    const int wrp  = t >> 5;             // warp id 0..3 -> cout group
    const int X0   = blockIdx.x << 3;
    const int Y0   = blockIdx.y << 3;

    // ---- load halo tile (zero-filled outside image) ----
    for (int f = t; f < 121 * 16; f += 128) {
        int cell = f >> 4;
        int q    = f & 15;                       // 16B chunk id (4 channels)
        int rr   = cell / 11;
        int cc   = cell - rr * 11;
        int gy   = Y0 - 1 + rr;
        int gx   = X0 - 1 + cc;
        float4 v = make_float4(0.f, 0.f, 0.f, 0.f);
        if ((unsigned)gy < (unsigned)IMG_H && (unsigned)gx < (unsigned)IMG_W)
            v = *reinterpret_cast<const float4*>(
                    &g_xT[(((gy << 8) + gx) << 6) + (q << 2)]);
        *reinterpret_cast<float4*>(
            &tile[(cell << 6) + ((q ^ (cell & 7)) << 2)]) = v;
    }
    __syncthreads();

    // sampling identity: 2 threads per pixel (32 channels each)
    const int px   = t & 63;
    const int half = t >> 6;             // 0 or 1 -> channel half
    const int pr   = px >> 3;
    const int pc   = px & 7;
    const int gy   = Y0 + pr;
    const int gx   = X0 + pc;
    const int pixidx = (gy << 8) + gx;

    u64 acc0[8], acc1[8];
#pragma unroll
    for (int j = 0; j < 8; ++j) { acc0[j] = 0ull; acc1[j] = 0ull; }

    int k = 0;
    for (int ky = 0; ky < 3; ++ky)
    for (int kx = 0; kx < 3; ++kx, ++k) {
        // -------- Phase A: bilinear sampling into sbuf --------
        {
            float offy = offs[(k * 2    ) * (IMG_H * IMG_W) + pixidx];
            float offx = offs[(k * 2 + 1) * (IMG_H * IMG_W) + pixidx];
            float pyf = (float)(gy - 1 + ky) + offy;
            float pxf = (float)(gx - 1 + kx) + offx;
            float y0f = floorf(pyf), x0f = floorf(pxf);
            int   y0  = (int)y0f,   x0  = (int)x0f;
            float wy1 = pyf - y0f,  wx1 = pxf - x0f;
            float wy0 = 1.f - wy1,  wx0 = 1.f - wx1;
            int iy = y0 - (Y0 - 1);
            int ix = x0 - (X0 - 1);
            // validity: image bounds (reference zero-pads) AND tile bounds (safety)
            float fy0 = ((unsigned)y0       < (unsigned)IMG_H && (unsigned)iy       <= 9u ) ? 1.f : 0.f;
            float fy1 = ((unsigned)(y0 + 1) < (unsigned)IMG_H && (unsigned)(iy + 1) <= 10u) ? 1.f : 0.f;
            float fx0 = ((unsigned)x0       < (unsigned)IMG_W && (unsigned)ix       <= 9u ) ? 1.f : 0.f;
            float fx1 = ((unsigned)(x0 + 1) < (unsigned)IMG_W && (unsigned)(ix + 1) <= 10u) ? 1.f : 0.f;
            float w00 = wy0 * wx0 * fy0 * fx0;
            float w01 = wy0 * wx1 * fy0 * fx1;
            float w10 = wy1 * wx0 * fy1 * fx0;
            float w11 = wy1 * wx1 * fy1 * fx1;
            int iyc = min(max(iy, 0), 9);
            int ixc = min(max(ix, 0), 9);
            int cell00 = iyc * 11 + ixc;
            int cell01 = cell00 + 1;
            int cell10 = cell00 + 11;
            int cell11 = cell00 + 12;
#pragma unroll
            for (int qq = 0; qq < 8; ++qq) {
                int q = (half << 3) + qq;
                float4 v00 = *reinterpret_cast<const float4*>(
                    &tile[(cell00 << 6) + ((q ^ (cell00 & 7)) << 2)]);
                float4 v01 = *reinterpret_cast<const float4*>(
                    &tile[(cell01 << 6) + ((q ^ (cell01 & 7)) << 2)]);
                float4 v10 = *reinterpret_cast<const float4*>(
                    &tile[(cell10 << 6) + ((q ^ (cell10 & 7)) << 2)]);
                float4 v11 = *reinterpret_cast<const float4*>(
                    &tile[(cell11 << 6) + ((q ^ (cell11 & 7)) << 2)]);
                float sx = fmaf(v11.x, w11, fmaf(v10.x, w10, fmaf(v01.x, w01, v00.x * w00)));
                float sy = fmaf(v11.y, w11, fmaf(v10.y, w10, fmaf(v01.y, w01, v00.y * w00)));
                float sz = fmaf(v11.z, w11, fmaf(v10.z, w10, fmaf(v01.z, w01, v00.z * w00)));
                float sw = fmaf(v11.w, w11, fmaf(v10.w, w10, fmaf(v01.w, w01, v00.w * w00)));
                int ch = q << 2;
                sbuf[((ch + 0) << 6) + px] = sx;
                sbuf[((ch + 1) << 6) + px] = sy;
                sbuf[((ch + 2) << 6) + px] = sz;
                sbuf[((ch + 3) << 6) + px] = sw;
            }
        }
        __syncthreads();

        // -------- Phase B: GEMM accumulate (packed f32x2) --------
        {
            // weight row for this tap / cout group; pairs of couts are contiguous
            const ulonglong2* wk2 = reinterpret_cast<const ulonglong2*>(
                g_wT + k * 4096 + (wrp << 4));
            const float* sp = sbuf + lane;
#pragma unroll 2
            for (int cin = 0; cin < 64; ++cin) {
                u64 s0 = splat2(sp[(cin << 6)]);
                u64 s1 = splat2(sp[(cin << 6) + 32]);
                ulonglong2 A = wk2[cin * 16 + 0];   // couts 16w..16w+3
                ulonglong2 Bq = wk2[cin * 16 + 1];  // 16w+4..7
                ulonglong2 Cq = wk2[cin * 16 + 2];  // 16w+8..11
                ulonglong2 Dq = wk2[cin * 16 + 3];  // 16w+12..15
                acc0[0] = fma2(A.x,  s0, acc0[0]);  acc1[0] = fma2(A.x,  s1, acc1[0]);
                acc0[1] = fma2(A.y,  s0, acc0[1]);  acc1[1] = fma2(A.y,  s1, acc1[1]);
                acc0[2] = fma2(Bq.x, s0, acc0[2]);  acc1[2] = fma2(Bq.x, s1, acc1[2]);
                acc0[3] = fma2(Bq.y, s0, acc0[3]);  acc1[3] = fma2(Bq.y, s1, acc1[3]);
                acc0[4] = fma2(Cq.x, s0, acc0[4]);  acc1[4] = fma2(Cq.x, s1, acc1[4]);
                acc0[5] = fma2(Cq.y, s0, acc0[5]);  acc1[5] = fma2(Cq.y, s1, acc1[5]);
                acc0[6] = fma2(Dq.x, s0, acc0[6]);  acc1[6] = fma2(Dq.x, s1, acc1[6]);
                acc0[7] = fma2(Dq.y, s0, acc0[7]);  acc1[7] = fma2(Dq.y, s1, acc1[7]);
            }
        }
        __syncthreads();
    }

    // -------- epilogue: bias + store --------
    const int coutBase = wrp << 4;
    {
        int p2 = lane;                    // pixel for acc0
        int oy = Y0 + (p2 >> 3), ox = X0 + (p2 & 7);
        int base = (oy << 8) + ox;
#pragma unroll
        for (int j = 0; j < 8; ++j) {
            float2 v = unpack2(acc0[j]);
            int co = coutBase + (j << 1);
            out[(co << 16) + base]       = v.x + bias[co];
            out[((co + 1) << 16) + base] = v.y + bias[co + 1];
        }
    }
    {
        int p2 = lane + 32;               // pixel for acc1
        int oy = Y0 + (p2 >> 3), ox = X0 + (p2 & 7);
        int base = (oy << 8) + ox;
#pragma unroll
        for (int j = 0; j < 8; ++j) {
            float2 v = unpack2(acc1[j]);
            int co = coutBase + (j << 1);
            out[(co << 16) + base]       = v.x + bias[co];
            out[((co + 1) << 16) + base] = v.y + bias[co + 1];
        }
    }
}

// ============================================================
// Launch
// ============================================================
extern "C" void kernel_launch(void* const* d_in, const int* in_sizes, int n_in,
                              void* d_out, int out_size) {
    const float* x      = nullptr;
    const float* offset = nullptr;
    const float* weight = nullptr;
    const float* bias   = nullptr;

    // identify inputs by element count (all distinct for this problem)
    for (int i = 0; i < n_in; ++i) {
        switch (in_sizes[i]) {
            case 64 * 256 * 256: x      = (const float*)d_in[i]; break;  // 4194304
            case 18 * 256 * 256: offset = (const float*)d_in[i]; break;  // 1179648
            case 64 * 64 * 9:    weight = (const float*)d_in[i]; break;  // 36864
            case 64:             bias   = (const float*)d_in[i]; break;
            default: break;
        }
    }
    // positional fallback (metadata order: x, offset, weight, bias)
    if (!x || !offset || !weight || !bias) {
        x      = (const float*)d_in[0];
        offset = (const float*)d_in[1];
        weight = (const float*)d_in[2];
        bias   = (const float*)d_in[3];
    }

    transpose_x_kernel<<<(IMG_H * IMG_W) / 64, 256>>>(x);
    prep_w_kernel<<<36, 1024>>>(weight);
    deform_main_kernel<<<dim3(IMG_W / 8, IMG_H / 8), 128>>>(
        offset, bias, (float*)d_out);
}

// round 6
// speedup vs baseline: 1.7762x; 1.7762x over previous
#include <cuda_runtime.h>
#include <cstdint>

// Problem constants: B=1, CIN=COUT=64, H=W=256, K=3, stride=1, pad=1.
#define IMG_H 256
#define IMG_W 256

// Scratch (device globals; no allocation allowed)
__device__ float g_xT[IMG_H * IMG_W * 64];   // x as (y, x, c) — 16 MB
__device__ float g_wT[9 * 64 * 64];          // weights as (k, cin, cout)

typedef unsigned long long u64;

// ---- packed fp32x2 helpers (sm_100+) ----
__device__ __forceinline__ u64 fma2(u64 a, u64 b, u64 c) {
    u64 d; asm("fma.rn.f32x2 %0, %1, %2, %3;" : "=l"(d) : "l"(a), "l"(b), "l"(c));
    return d;
}
__device__ __forceinline__ u64 mul2(u64 a, u64 b) {
    u64 d; asm("mul.rn.f32x2 %0, %1, %2;" : "=l"(d) : "l"(a), "l"(b));
    return d;
}
__device__ __forceinline__ u64 splat2(float x) {
    unsigned r = __float_as_uint(x);
    u64 d; asm("mov.b64 %0, {%1, %2};" : "=l"(d) : "r"(r), "r"(r));
    return d;
}
__device__ __forceinline__ float2 unpack2(u64 v) {
    unsigned lo, hi;
    asm("mov.b64 {%0, %1}, %2;" : "=r"(lo), "=r"(hi) : "l"(v));
    return make_float2(__uint_as_float(lo), __uint_as_float(hi));
}

// ============================================================
// Kernel 1: transpose x (C,H,W) -> (H,W,C)
// ============================================================
__global__ void transpose_x_kernel(const float* __restrict__ x) {
    __shared__ float ts[64][65];
    const int t  = threadIdx.x;          // 256 threads
    const int tx = t & 63;
    const int ty = t >> 6;
    const int P0 = blockIdx.x * 64;
#pragma unroll
    for (int i = 0; i < 16; ++i) {
        int c = (i << 2) + ty;
        ts[c][tx] = x[c * (IMG_H * IMG_W) + P0 + tx];
    }
    __syncthreads();
#pragma unroll
    for (int i = 0; i < 16; ++i) {
        int p = (i << 2) + ty;
        g_xT[(P0 + p) * 64 + tx] = ts[tx][p];
    }
}

// ============================================================
// Kernel 2: weight relayout (cout,cin,k) -> (k,cin,cout)
// ============================================================
__global__ void prep_w_kernel(const float* __restrict__ wsrc) {
    int idx = blockIdx.x * blockDim.x + threadIdx.x;
    if (idx >= 64 * 64 * 9) return;
    int cout = idx / 576;
    int r    = idx - cout * 576;
    int cin  = r / 9;
    int k    = r - cin * 9;
    g_wT[(k * 64 + cin) * 64 + cout] = wsrc[idx];
}

// ============================================================
// Kernel 3: main deformable conv
//   Tile: 16x8 = 128 output px, 256 threads (8 warps), occ 2.
//   smem (dynamic, 102656 B):
//     tile : 19x11 halo cells x 64 ch (53504 B, XOR-swizzled 16B chunks)
//     sbuf : s[cin=64][px=128]          (32768 B)
//     wsm  : weights of current tap, [cin=64][cout=64] (16384 B)
//   Per tap: Phase A bilinear-sample -> sbuf; Phase B register GEMM
//   with fp32x2 FMA, weights via smem broadcast (prefetched one tap ahead).
// ============================================================
extern __shared__ float sm_dyn[];

__global__ __launch_bounds__(256, 2)
void deform_main_kernel(const float* __restrict__ offs,
                        const float* __restrict__ bias,
                        float* __restrict__ out) {
    float* tile = sm_dyn;                  // 19*11*64 = 13376 floats
    float* sbuf = sm_dyn + 13376;          // 64*128   =  8192 floats
    float* wsm  = sm_dyn + 13376 + 8192;   // 64*64    =  4096 floats

    const int t    = threadIdx.x;
    const int lane = t & 31;
    const int wrp  = t >> 5;               // 0..7 -> cout group (8 couts)
    const int X0   = blockIdx.x << 3;      // 8 wide
    const int Y0   = blockIdx.y << 4;      // 16 tall

    // ---- load halo tile: 19 rows x 11 cols x 64 ch (zero outside image) ----
    for (int f = t; f < 209 * 16; f += 256) {
        int cell = f >> 4;
        int q    = f & 15;
        int rr   = cell / 11;
        int cc   = cell - rr * 11;
        int gy   = Y0 - 1 + rr;
        int gx   = X0 - 1 + cc;
        float4 v = make_float4(0.f, 0.f, 0.f, 0.f);
        if ((unsigned)gy < (unsigned)IMG_H && (unsigned)gx < (unsigned)IMG_W)
            v = *reinterpret_cast<const float4*>(
                    &g_xT[(((gy << 8) + gx) << 6) + (q << 2)]);
        *reinterpret_cast<float4*>(
            &tile[(cell << 6) + ((q ^ (cell & 7)) << 2)]) = v;
    }

    // ---- prefetch weights of tap 0 into registers, stage into wsm ----
    float4 wr[4];
#pragma unroll
    for (int i = 0; i < 4; ++i)
        wr[i] = *reinterpret_cast<const float4*>(&g_wT[((i << 8) + t) << 2]);
#pragma unroll
    for (int i = 0; i < 4; ++i)
        *reinterpret_cast<float4*>(&wsm[((i << 8) + t) << 2]) = wr[i];
    __syncthreads();

    // sampling identity: 2 threads per pixel (32 channels each)
    const int px   = t & 127;
    const int half = t >> 7;
    const int pr   = px >> 3;               // 0..15
    const int pc   = px & 7;
    const int gy   = Y0 + pr;
    const int gx   = X0 + pc;
    const int pixidx = (gy << 8) + gx;

    u64 acc[4][4];                          // [cout pair][px]
#pragma unroll
    for (int a = 0; a < 4; ++a)
#pragma unroll
        for (int b = 0; b < 4; ++b) acc[a][b] = 0ull;

#pragma unroll 1
    for (int k = 0; k < 9; ++k) {
        const int ky = k / 3;
        const int kx = k - ky * 3;

        // stage weights of tap k into wsm (prologue did k=0)
        if (k > 0) {
#pragma unroll
            for (int i = 0; i < 4; ++i)
                *reinterpret_cast<float4*>(&wsm[((i << 8) + t) << 2]) = wr[i];
        }

        // -------- Phase A: bilinear sampling into sbuf --------
        {
            float offy = offs[(k * 2    ) * (IMG_H * IMG_W) + pixidx];
            float offx = offs[(k * 2 + 1) * (IMG_H * IMG_W) + pixidx];
            float pyf = (float)(gy - 1 + ky) + offy;
            float pxf = (float)(gx - 1 + kx) + offx;
            float y0f = floorf(pyf), x0f = floorf(pxf);
            int   y0  = (int)y0f,   x0  = (int)x0f;
            float wy1 = pyf - y0f,  wx1 = pxf - x0f;
            float wy0 = 1.f - wy1,  wx0 = 1.f - wx1;
            int iy = y0 - (Y0 - 1);
            int ix = x0 - (X0 - 1);
            // validity: image bounds (zero pad) AND tile bounds (safety)
            float fy0 = ((unsigned)y0       < (unsigned)IMG_H && (unsigned)iy       <= 17u) ? 1.f : 0.f;
            float fy1 = ((unsigned)(y0 + 1) < (unsigned)IMG_H && (unsigned)(iy + 1) <= 18u) ? 1.f : 0.f;
            float fx0 = ((unsigned)x0       < (unsigned)IMG_W && (unsigned)ix       <=  9u) ? 1.f : 0.f;
            float fx1 = ((unsigned)(x0 + 1) < (unsigned)IMG_W && (unsigned)(ix + 1) <= 10u) ? 1.f : 0.f;
            u64 W00 = splat2(wy0 * wx0 * fy0 * fx0);
            u64 W01 = splat2(wy0 * wx1 * fy0 * fx1);
            u64 W10 = splat2(wy1 * wx0 * fy1 * fx0);
            u64 W11 = splat2(wy1 * wx1 * fy1 * fx1);
            int iyc = min(max(iy, 0), 17);
            int ixc = min(max(ix, 0), 9);
            int c00 = iyc * 11 + ixc;
            int c01 = c00 + 1;
            int c10 = c00 + 11;
            int c11 = c00 + 12;
#pragma unroll
            for (int qq = 0; qq < 8; ++qq) {
                int q = (half << 3) + qq;
                ulonglong2 v00 = *reinterpret_cast<const ulonglong2*>(
                    &tile[(c00 << 6) + ((q ^ (c00 & 7)) << 2)]);
                ulonglong2 v01 = *reinterpret_cast<const ulonglong2*>(
                    &tile[(c01 << 6) + ((q ^ (c01 & 7)) << 2)]);
                ulonglong2 v10 = *reinterpret_cast<const ulonglong2*>(
                    &tile[(c10 << 6) + ((q ^ (c10 & 7)) << 2)]);
                ulonglong2 v11 = *reinterpret_cast<const ulonglong2*>(
                    &tile[(c11 << 6) + ((q ^ (c11 & 7)) << 2)]);
                u64 lo = fma2(v00.x, W00, fma2(v01.x, W01, fma2(v10.x, W10, mul2(v11.x, W11))));
                u64 hi = fma2(v00.y, W00, fma2(v01.y, W01, fma2(v10.y, W10, mul2(v11.y, W11))));
                float2 flo = unpack2(lo);
                float2 fhi = unpack2(hi);
                int ch = q << 2;
                sbuf[((ch + 0) << 7) + px] = flo.x;
                sbuf[((ch + 1) << 7) + px] = flo.y;
                sbuf[((ch + 2) << 7) + px] = fhi.x;
                sbuf[((ch + 3) << 7) + px] = fhi.y;
            }
        }

        // prefetch weights of next tap (consumed at top of next iteration)
        if (k < 8) {
#pragma unroll
            for (int i = 0; i < 4; ++i)
                wr[i] = *reinterpret_cast<const float4*>(
                    &g_wT[(k + 1) * 4096 + (((i << 8) + t) << 2)]);
        }
        __syncthreads();   // sbuf + wsm ready

        // -------- Phase B: GEMM accumulate (packed f32x2) --------
        {
            const float4* sp = reinterpret_cast<const float4*>(sbuf) + lane;
            const ulonglong2* wp =
                reinterpret_cast<const ulonglong2*>(wsm + (wrp << 3));
#pragma unroll 8
            for (int cin = 0; cin < 64; ++cin) {
                float4 s = sp[cin << 5];
                u64 s0 = splat2(s.x);
                u64 s1 = splat2(s.y);
                u64 s2 = splat2(s.z);
                u64 s3 = splat2(s.w);
                ulonglong2 wa = wp[(cin << 4)];       // couts 8w..8w+3
                ulonglong2 wb = wp[(cin << 4) + 1];   // couts 8w+4..8w+7
                acc[0][0] = fma2(wa.x, s0, acc[0][0]);
                acc[0][1] = fma2(wa.x, s1, acc[0][1]);
                acc[0][2] = fma2(wa.x, s2, acc[0][2]);
                acc[0][3] = fma2(wa.x, s3, acc[0][3]);
                acc[1][0] = fma2(wa.y, s0, acc[1][0]);
                acc[1][1] = fma2(wa.y, s1, acc[1][1]);
                acc[1][2] = fma2(wa.y, s2, acc[1][2]);
                acc[1][3] = fma2(wa.y, s3, acc[1][3]);
                acc[2][0] = fma2(wb.x, s0, acc[2][0]);
                acc[2][1] = fma2(wb.x, s1, acc[2][1]);
                acc[2][2] = fma2(wb.x, s2, acc[2][2]);
                acc[2][3] = fma2(wb.x, s3, acc[2][3]);
                acc[3][0] = fma2(wb.y, s0, acc[3][0]);
                acc[3][1] = fma2(wb.y, s1, acc[3][1]);
                acc[3][2] = fma2(wb.y, s2, acc[3][2]);
                acc[3][3] = fma2(wb.y, s3, acc[3][3]);
            }
        }
        __syncthreads();   // sbuf & wsm consumed
    }

    // -------- epilogue: bias + vectorized store --------
    // lane owns px 4*lane .. 4*lane+3 (contiguous in a row)
    {
        int ep_gy = Y0 + (lane >> 1);
        int ep_gx = X0 + ((lane & 1) << 2);
        int base  = (ep_gy << 8) + ep_gx;
#pragma unroll
        for (int pair = 0; pair < 4; ++pair) {
            int c0 = (wrp << 3) + (pair << 1);
            float b0 = bias[c0], b1 = bias[c0 + 1];
            float2 v0 = unpack2(acc[pair][0]);
            float2 v1 = unpack2(acc[pair][1]);
            float2 v2 = unpack2(acc[pair][2]);
            float2 v3 = unpack2(acc[pair][3]);
            float4 o0 = make_float4(v0.x + b0, v1.x + b0, v2.x + b0, v3.x + b0);
            float4 o1 = make_float4(v0.y + b1, v1.y + b1, v2.y + b1, v3.y + b1);
            *reinterpret_cast<float4*>(&out[(c0 << 16) + base])       = o0;
            *reinterpret_cast<float4*>(&out[((c0 + 1) << 16) + base]) = o1;
        }
    }
}

// ============================================================
// Launch
// ============================================================
extern "C" void kernel_launch(void* const* d_in, const int* in_sizes, int n_in,
                              void* d_out, int out_size) {
    const float* x      = nullptr;
    const float* offset = nullptr;
    const float* weight = nullptr;
    const float* bias   = nullptr;

    for (int i = 0; i < n_in; ++i) {
        switch (in_sizes[i]) {
            case 64 * 256 * 256: x      = (const float*)d_in[i]; break;
            case 18 * 256 * 256: offset = (const float*)d_in[i]; break;
            case 64 * 64 * 9:    weight = (const float*)d_in[i]; break;
            case 64:             bias   = (const float*)d_in[i]; break;
            default: break;
        }
    }
    if (!x || !offset || !weight || !bias) {
        x      = (const float*)d_in[0];
        offset = (const float*)d_in[1];
        weight = (const float*)d_in[2];
        bias   = (const float*)d_in[3];
    }

    const int SMEM_BYTES = (13376 + 8192 + 4096) * 4;   // 102656
    cudaFuncSetAttribute(deform_main_kernel,
                         cudaFuncAttributeMaxDynamicSharedMemorySize, SMEM_BYTES);

    transpose_x_kernel<<<(IMG_H * IMG_W) / 64, 256>>>(x);
    prep_w_kernel<<<36, 1024>>>(weight);
    deform_main_kernel<<<dim3(IMG_W / 8, IMG_H / 16), 256, SMEM_BYTES>>>(
        offset, bias, (float*)d_out);
}

// round 8
// speedup vs baseline: 2.7972x; 1.5748x over previous
#include <cuda_runtime.h>
#include <cuda_bf16.h>
#include <cstdint>

// Problem constants: B=1, CIN=COUT=64, H=W=256, K=3, stride=1, pad=1.
#define IMG_H 256
#define IMG_W 256

// ---- device scratch (no allocation allowed) ----
__device__ float g_xT[IMG_H * IMG_W * 64];   // x as (y, x, c) fp32
__device__ uint4 g_wh[9 * 512];              // per-tap W tile [cout=64][cin=64] bf16, SW128-preswizzled, hi
__device__ uint4 g_wl[9 * 512];              // ... lo

typedef unsigned long long u64;

// ---- packed fp32x2 helpers ----
__device__ __forceinline__ u64 fma2(u64 a, u64 b, u64 c) {
    u64 d; asm("fma.rn.f32x2 %0, %1, %2, %3;" : "=l"(d) : "l"(a), "l"(b), "l"(c));
    return d;
}
__device__ __forceinline__ u64 mul2(u64 a, u64 b) {
    u64 d; asm("mul.rn.f32x2 %0, %1, %2;" : "=l"(d) : "l"(a), "l"(b));
    return d;
}
__device__ __forceinline__ u64 splat2(float x) {
    unsigned r = __float_as_uint(x);
    u64 d; asm("mov.b64 %0, {%1, %2};" : "=l"(d) : "r"(r), "r"(r));
    return d;
}
__device__ __forceinline__ float2 unpack2(u64 v) {
    unsigned lo, hi;
    asm("mov.b64 {%0, %1}, %2;" : "=r"(lo), "=r"(hi) : "l"(v));
    return make_float2(__uint_as_float(lo), __uint_as_float(hi));
}

// ---- legacy tensor-core helpers (sm_80 path; compiles for compute_100) ----
__device__ __forceinline__ uint32_t smem_u32_of(const void* p) {
    uint32_t a;
    asm("{ .reg .u64 t; cvta.to.shared.u64 t, %1; cvt.u32.u64 %0, t; }"
        : "=r"(a) : "l"(p));
    return a;
}
__device__ __forceinline__ void ldsm4(uint32_t* r, uint32_t addr) {
    asm volatile("ldmatrix.sync.aligned.m8n8.x4.shared.b16 {%0,%1,%2,%3}, [%4];"
        : "=r"(r[0]), "=r"(r[1]), "=r"(r[2]), "=r"(r[3]) : "r"(addr));
}
__device__ __forceinline__ void ldsm2(uint32_t* r, uint32_t addr) {
    asm volatile("ldmatrix.sync.aligned.m8n8.x2.shared.b16 {%0,%1}, [%2];"
        : "=r"(r[0]), "=r"(r[1]) : "r"(addr));
}
__device__ __forceinline__ void mma_bf16(float* c, const uint32_t* a, const uint32_t* b) {
    asm volatile(
        "mma.sync.aligned.m16n8k16.row.col.f32.bf16.bf16.f32 "
        "{%0,%1,%2,%3}, {%4,%5,%6,%7}, {%8,%9}, {%0,%1,%2,%3};"
        : "+f"(c[0]), "+f"(c[1]), "+f"(c[2]), "+f"(c[3])
        : "r"(a[0]), "r"(a[1]), "r"(a[2]), "r"(a[3]), "r"(b[0]), "r"(b[1]));
}

// ---- smem layout (bytes from dynamic base) ----
#define OFF_BIAS   0         // 64 floats
#define OFF_TILE   1024      // halo fp32: 19*11*64*4 = 53504
#define OFF_AH     55296     // samples hi: 128x64 bf16 = 16384
#define OFF_AL     71680     // samples lo: 16384
#define OFF_WH     88064     // weights hi: 64x64 bf16 = 8192
#define OFF_WL     96256     // weights lo: 8192
#define SMEM_TOTAL 104448

// ============================================================
// Kernel 1: transpose x (C,H,W) -> (H,W,C)
// ============================================================
__global__ void transpose_x_kernel(const float* __restrict__ x) {
    __shared__ float ts[64][65];
    const int t  = threadIdx.x;
    const int tx = t & 63;
    const int ty = t >> 6;
    const int P0 = blockIdx.x * 64;
#pragma unroll
    for (int i = 0; i < 16; ++i) {
        int c = (i << 2) + ty;
        ts[c][tx] = x[c * (IMG_H * IMG_W) + P0 + tx];
    }
    __syncthreads();
#pragma unroll
    for (int i = 0; i < 16; ++i) {
        int p = (i << 2) + ty;
        g_xT[(P0 + p) * 64 + tx] = ts[tx][p];
    }
}

// ============================================================
// Kernel 2: weight split bf16 hi/lo, relayout per-tap [cout][cin], SW128 swizzle
// ============================================================
__global__ void prep_w_kernel(const float* __restrict__ wsrc) {
    int idx = blockIdx.x * blockDim.x + threadIdx.x;   // over (cout,cin,k)
    if (idx >= 64 * 64 * 9) return;
    int cout = idx / 576;
    int r    = idx - cout * 576;
    int cin  = r / 9;
    int k    = r - cin * 9;
    float v  = wsrc[idx];
    __nv_bfloat16 hb = __float2bfloat16(v);
    float hv = __bfloat162float(hb);
    __nv_bfloat16 lb = __float2bfloat16(v - hv);
    uint32_t off = (cout << 7) + (cin << 1);
    uint32_t sw  = off ^ ((off >> 3) & 0x70);
    ((__nv_bfloat16*)g_wh)[k * 4096 + (sw >> 1)] = hb;
    ((__nv_bfloat16*)g_wl)[k * 4096 + (sw >> 1)] = lb;
}

// ============================================================
// Kernel 3: main — per tap: sample -> bf16 hi/lo A tile; warp MMA (HMMA.16816)
//   Block: 16x8 px tile, 256 threads (8 warps), 2 blocks/SM.
//   D = W(64cout x 64cin) @ S^T(64cin x 128px), 3-term bf16 split.
//   Warp w: all 64 couts (4 m-tiles) x 16 px (2 n-tiles).
// ============================================================
extern __shared__ char smc[];

__global__ __launch_bounds__(256, 2)
void deform_main_kernel(const float* __restrict__ offs,
                        const float* __restrict__ bias,
                        float* __restrict__ out) {
    float* tile = (float*)(smc + OFF_TILE);
    const uint32_t smb = smem_u32_of(smc);

    const int t    = threadIdx.x;
    const int lane = t & 31;
    const int wid  = t >> 5;
    const int X0   = blockIdx.x << 3;      // 8 wide
    const int Y0   = blockIdx.y << 4;      // 16 tall

    if (t < 64) ((float*)(smc + OFF_BIAS))[t] = bias[t];

    // ---- halo tile: 19 rows x 11 cols x 64 ch fp32 (zero outside image) ----
    for (int f = t; f < 209 * 16; f += 256) {
        int cell = f >> 4;
        int q    = f & 15;
        int rr   = cell / 11;
        int cc   = cell - rr * 11;
        int gy   = Y0 - 1 + rr;
        int gx   = X0 - 1 + cc;
        float4 v = make_float4(0.f, 0.f, 0.f, 0.f);
        if ((unsigned)gy < (unsigned)IMG_H && (unsigned)gx < (unsigned)IMG_W)
            v = *reinterpret_cast<const float4*>(
                    &g_xT[(((gy << 8) + gx) << 6) + (q << 2)]);
        *reinterpret_cast<float4*>(
            &tile[(cell << 6) + ((q ^ (cell & 7)) << 2)]) = v;
    }
    __syncthreads();

    // sampling identity: 2 threads per pixel (32 channels each)
    const int px   = t & 127;
    const int half = t >> 7;
    const int gy   = Y0 + (px >> 3);
    const int gx   = X0 + (px & 7);
    const int pixidx = (gy << 8) + gx;

    // mma identity
    const int wpx0  = wid << 4;            // warp's first pixel
    const int lane7 = lane & 7;
    const int a_row0 = (lane & 7) + (lane & 8);   // ldmatrix x4 quad rows
    const int a_kbit = lane >> 4;                  // 0/1 -> k chunk +1
    const int b_rowl = wpx0 + (lane & 7);          // + nt*8
    const int b_kbit = (lane >> 3) & 1;

    float acc[4][2][4];                    // [m-tile][n-tile][frag]
#pragma unroll
    for (int m = 0; m < 4; ++m)
#pragma unroll
        for (int n = 0; n < 2; ++n)
#pragma unroll
            for (int j = 0; j < 4; ++j) acc[m][n][j] = 0.f;

#pragma unroll 1
    for (int k = 0; k < 9; ++k) {
        const int ky = k / 3;
        const int kx = k - ky * 3;

        // ---- stage W tap k (pre-swizzled 16B copies) ----
        {
            const uint4* wh = g_wh + k * 512;
            const uint4* wl = g_wl + k * 512;
            uint4* dh = (uint4*)(smc + OFF_WH);
            uint4* dl = (uint4*)(smc + OFF_WL);
            dh[t] = wh[t];  dh[t + 256] = wh[t + 256];
            dl[t] = wl[t];  dl[t + 256] = wl[t + 256];
        }

        // ---- bilinear sample -> bf16 hi/lo A tile (SW128 swizzle) ----
        {
            float offy = offs[(k * 2    ) * (IMG_H * IMG_W) + pixidx];
            float offx = offs[(k * 2 + 1) * (IMG_H * IMG_W) + pixidx];
            float pyf = (float)(gy - 1 + ky) + offy;
            float pxf = (float)(gx - 1 + kx) + offx;
            float y0f = floorf(pyf), x0f = floorf(pxf);
            int   y0  = (int)y0f,   x0  = (int)x0f;
            float wy1 = pyf - y0f,  wx1 = pxf - x0f;
            float wy0 = 1.f - wy1,  wx0 = 1.f - wx1;
            int iy = y0 - (Y0 - 1);
            int ix = x0 - (X0 - 1);
            float fy0 = ((unsigned)y0       < (unsigned)IMG_H && (unsigned)iy       <= 17u) ? 1.f : 0.f;
            float fy1 = ((unsigned)(y0 + 1) < (unsigned)IMG_H && (unsigned)(iy + 1) <= 18u) ? 1.f : 0.f;
            float fx0 = ((unsigned)x0       < (unsigned)IMG_W && (unsigned)ix       <=  9u) ? 1.f : 0.f;
            float fx1 = ((unsigned)(x0 + 1) < (unsigned)IMG_W && (unsigned)(ix + 1) <= 10u) ? 1.f : 0.f;
            u64 W00 = splat2(wy0 * wx0 * fy0 * fx0);
            u64 W01 = splat2(wy0 * wx1 * fy0 * fx1);
            u64 W10 = splat2(wy1 * wx0 * fy1 * fx0);
            u64 W11 = splat2(wy1 * wx1 * fy1 * fx1);
            int iyc = min(max(iy, 0), 17);
            int ixc = min(max(ix, 0), 9);
            int c00 = iyc * 11 + ixc;
            int c01 = c00 + 1;
            int c10 = c00 + 11;
            int c11 = c00 + 12;
            char* abase = smc + OFF_AH;
#pragma unroll
            for (int qq = 0; qq < 8; ++qq) {
                int q = (half << 3) + qq;
                ulonglong2 v00 = *reinterpret_cast<const ulonglong2*>(
                    &tile[(c00 << 6) + ((q ^ (c00 & 7)) << 2)]);
                ulonglong2 v01 = *reinterpret_cast<const ulonglong2*>(
                    &tile[(c01 << 6) + ((q ^ (c01 & 7)) << 2)]);
                ulonglong2 v10 = *reinterpret_cast<const ulonglong2*>(
                    &tile[(c10 << 6) + ((q ^ (c10 & 7)) << 2)]);
                ulonglong2 v11 = *reinterpret_cast<const ulonglong2*>(
                    &tile[(c11 << 6) + ((q ^ (c11 & 7)) << 2)]);
                u64 lo2 = fma2(v00.x, W00, fma2(v01.x, W01, fma2(v10.x, W10, mul2(v11.x, W11))));
                u64 hi2 = fma2(v00.y, W00, fma2(v01.y, W01, fma2(v10.y, W10, mul2(v11.y, W11))));
                float2 fa = unpack2(lo2);   // ch q*4+0, +1
                float2 fb = unpack2(hi2);   // ch q*4+2, +3
                uint32_t h01, h23;
                asm("cvt.rn.satfinite.bf16x2.f32 %0, %1, %2;" : "=r"(h01) : "f"(fa.y), "f"(fa.x));
                asm("cvt.rn.satfinite.bf16x2.f32 %0, %1, %2;" : "=r"(h23) : "f"(fb.y), "f"(fb.x));
                float r0 = fa.x - __uint_as_float(h01 << 16);
                float r1 = fa.y - __uint_as_float(h01 & 0xffff0000u);
                float r2 = fb.x - __uint_as_float(h23 << 16);
                float r3 = fb.y - __uint_as_float(h23 & 0xffff0000u);
                uint32_t l01, l23;
                asm("cvt.rn.satfinite.bf16x2.f32 %0, %1, %2;" : "=r"(l01) : "f"(r1), "f"(r0));
                asm("cvt.rn.satfinite.bf16x2.f32 %0, %1, %2;" : "=r"(l23) : "f"(r3), "f"(r2));
                uint32_t aoff = (px << 7) + (q << 3);
                uint32_t sw   = aoff ^ ((aoff >> 3) & 0x70);
                *reinterpret_cast<uint2*>(abase + sw)         = make_uint2(h01, h23);
                *reinterpret_cast<uint2*>(abase + 16384 + sw) = make_uint2(l01, l23);
            }
        }
        __syncthreads();   // A + W tiles ready

        // ---- MMA phase: 96 HMMA per warp (hh + hl + lh) ----
#pragma unroll
        for (int kt = 0; kt < 4; ++kt) {
            uint32_t bh0[2], bh1[2], bl0[2], bl1[2];
            {
                uint32_t bsw0 = (uint32_t)(((kt * 2 + b_kbit) ^ lane7) << 4);
                uint32_t ba0  = smb + OFF_AH + ((uint32_t)b_rowl << 7) + bsw0;
                uint32_t ba1  = ba0 + (8 << 7);
                ldsm2(bh0, ba0);          ldsm2(bh1, ba1);
                ldsm2(bl0, ba0 + 16384);  ldsm2(bl1, ba1 + 16384);
            }
#pragma unroll
            for (int mt = 0; mt < 4; ++mt) {
                uint32_t ah[4], al[4];
                uint32_t asw = (uint32_t)(((kt * 2 + a_kbit) ^ lane7) << 4);
                uint32_t aa  = smb + OFF_WH + (((uint32_t)(mt * 16 + a_row0)) << 7) + asw;
                ldsm4(ah, aa);
                ldsm4(al, aa + 8192);
                mma_bf16(acc[mt][0], ah, bh0);
                mma_bf16(acc[mt][1], ah, bh1);
                mma_bf16(acc[mt][0], ah, bl0);
                mma_bf16(acc[mt][1], ah, bl1);
                mma_bf16(acc[mt][0], al, bh0);
                mma_bf16(acc[mt][1], al, bh1);
            }
        }
        __syncthreads();   // tiles consumed; next tap may overwrite
    }

    // ---- epilogue: bias + float2 stores ----
    // D frag: c0,c1 -> (cout = mt*16 + lane/4,     px pair)
    //         c2,c3 -> (cout = mt*16 + lane/4 + 8, px pair)
    {
        const float* sbias = (const float*)(smc + OFF_BIAS);
        int tg  = lane >> 2;
        int tc2 = (lane & 3) << 1;
#pragma unroll
        for (int mt = 0; mt < 4; ++mt) {
#pragma unroll
            for (int nt = 0; nt < 2; ++nt) {
                int p   = wpx0 + nt * 8 + tc2;
                int pix = ((Y0 + (p >> 3)) << 8) + X0 + (p & 7);
                int c0  = mt * 16 + tg;
                int c1  = c0 + 8;
                float b0 = sbias[c0], b1 = sbias[c1];
                *reinterpret_cast<float2*>(&out[(c0 << 16) + pix]) =
                    make_float2(acc[mt][nt][0] + b0, acc[mt][nt][1] + b0);
                *reinterpret_cast<float2*>(&out[(c1 << 16) + pix]) =
                    make_float2(acc[mt][nt][2] + b1, acc[mt][nt][3] + b1);
            }
        }
    }
}

// ============================================================
// Launch
// ============================================================
extern "C" void kernel_launch(void* const* d_in, const int* in_sizes, int n_in,
                              void* d_out, int out_size) {
    const float* x      = nullptr;
    const float* offset = nullptr;
    const float* weight = nullptr;
    const float* bias   = nullptr;

    for (int i = 0; i < n_in; ++i) {
        switch (in_sizes[i]) {
            case 64 * 256 * 256: x      = (const float*)d_in[i]; break;
            case 18 * 256 * 256: offset = (const float*)d_in[i]; break;
            case 64 * 64 * 9:    weight = (const float*)d_in[i]; break;
            case 64:             bias   = (const float*)d_in[i]; break;
            default: break;
        }
    }
    if (!x || !offset || !weight || !bias) {
        x      = (const float*)d_in[0];
        offset = (const float*)d_in[1];
        weight = (const float*)d_in[2];
        bias   = (const float*)d_in[3];
    }

    cudaFuncSetAttribute(deform_main_kernel,
                         cudaFuncAttributeMaxDynamicSharedMemorySize, SMEM_TOTAL);

    transpose_x_kernel<<<(IMG_H * IMG_W) / 64, 256>>>(x);
    prep_w_kernel<<<36, 1024>>>(weight);
    deform_main_kernel<<<dim3(IMG_W / 8, IMG_H / 16), 256, SMEM_TOTAL>>>(
        offset, bias, (float*)d_out);
}